// round 11
// baseline (speedup 1.0000x reference)
#include <cuda_runtime.h>
#include <cuda_bf16.h>
#include <cstdint>
#include <math.h>

#define NTOK 6144
#define DMODEL 256
#define NHEAD 8
#define DKH 32
#define NLAYER 2
#define NVOCAB 1024
#define LSEQ 96
#define NBATCH 64

typedef __nv_bfloat16 bf16;
typedef __nv_bfloat162 bf162;

// ---------------------------------------------------------------------------
// Scratch
// ---------------------------------------------------------------------------
__device__ float g_x  [NTOK * DMODEL];
__device__ bf16  g_qkvb[NTOK * 3 * DMODEL];
__device__ bf16  g_xn [NTOK * DMODEL];
__device__ bf16  g_att[NTOK * DMODEL];
__device__ bf16  g_mid[NTOK * 4 * DMODEL];
__device__ bf16  g_xb [NTOK * DMODEL];
__device__ bf16 g_wqkv[NLAYER * DMODEL * 3 * DMODEL];
__device__ bf16 g_wo  [NLAYER * DMODEL * DMODEL];
__device__ bf16 g_wf1 [NLAYER * DMODEL * 4 * DMODEL];
__device__ bf16 g_wf2 [NLAYER * 4 * DMODEL * DMODEL];
__device__ bf16 g_wgen[DMODEL * NVOCAB];

// ---------------------------------------------------------------------------
// helpers
// ---------------------------------------------------------------------------
__device__ __forceinline__ unsigned pk2(float a, float b)
{
    bf162 t = __floats2bfloat162_rn(a, b);
    return *(unsigned*)&t;
}

__device__ __forceinline__ void mma_bf16(float* c, unsigned a0, unsigned a1,
                                         unsigned a2, unsigned a3,
                                         unsigned b0, unsigned b1)
{
    asm volatile(
        "mma.sync.aligned.m16n8k16.row.col.f32.bf16.bf16.f32 "
        "{%0,%1,%2,%3}, {%4,%5,%6,%7}, {%8,%9}, {%0,%1,%2,%3};"
        : "+f"(c[0]), "+f"(c[1]), "+f"(c[2]), "+f"(c[3])
        : "r"(a0), "r"(a1), "r"(a2), "r"(a3), "r"(b0), "r"(b1));
}

__device__ __forceinline__ void ldsm4(unsigned& r0, unsigned& r1,
                                      unsigned& r2, unsigned& r3, const void* p)
{
    unsigned a = (unsigned)__cvta_generic_to_shared(p);
    asm volatile("ldmatrix.sync.aligned.m8n8.x4.shared.b16 {%0,%1,%2,%3}, [%4];"
                 : "=r"(r0), "=r"(r1), "=r"(r2), "=r"(r3) : "r"(a));
}

__device__ __forceinline__ void ldsm4t(unsigned& r0, unsigned& r1,
                                       unsigned& r2, unsigned& r3, const void* p)
{
    unsigned a = (unsigned)__cvta_generic_to_shared(p);
    asm volatile("ldmatrix.sync.aligned.m8n8.x4.trans.shared.b16 {%0,%1,%2,%3}, [%4];"
                 : "=r"(r0), "=r"(r1), "=r"(r2), "=r"(r3) : "r"(a));
}

__device__ __forceinline__ void cpa16(void* smem_dst, const void* gsrc)
{
    unsigned s = (unsigned)__cvta_generic_to_shared(smem_dst);
    asm volatile("cp.async.cg.shared.global [%0], [%1], 16;\n" :: "r"(s), "l"(gsrc));
}
__device__ __forceinline__ void cpa_commit()
{
    asm volatile("cp.async.commit_group;\n" ::: "memory");
}
__device__ __forceinline__ void cpa_wait1()
{
    asm volatile("cp.async.wait_group 1;\n" ::: "memory");
}

// ---------------------------------------------------------------------------
// Fused fp32->bf16 conversion of all 5 weight tensors (one launch)
// ---------------------------------------------------------------------------
__global__ void cvt5_k(const float4* __restrict__ q,  const float4* __restrict__ o,
                       const float4* __restrict__ f1, const float4* __restrict__ f2,
                       const float4* __restrict__ gw,
                       uint2* __restrict__ qd,  uint2* __restrict__ od,
                       uint2* __restrict__ f1d, uint2* __restrict__ f2d,
                       uint2* __restrict__ gd)
{
    int i = blockIdx.x * 256 + threadIdx.x;
    const float4* s; uint2* d; int j = i;
    if (j < 98304)                    { s = q;  d = qd;  }
    else if ((j -= 98304)  < 32768)   { s = o;  d = od;  }
    else if ((j -= 32768)  < 131072)  { s = f1; d = f1d; }
    else if ((j -= 131072) < 131072)  { s = f2; d = f2d; }
    else { j -= 131072;                 s = gw; d = gd;  }
    float4 v = s[j];
    uint2 u;
    u.x = pk2(v.x, v.y);
    u.y = pk2(v.z, v.w);
    d[j] = u;
}

// ---------------------------------------------------------------------------
// Embedding
// ---------------------------------------------------------------------------
__global__ void embed_k(const int* __restrict__ tok, const int* __restrict__ pos,
                        const float* __restrict__ ve, const float* __restrict__ ce,
                        const float* __restrict__ pe, float* __restrict__ x)
{
    int n = blockIdx.x;
    int d = threadIdx.x;
    int p = pos[n];
    x[n * DMODEL + d] = ce[(p % 3) * DMODEL + d]
                      + pe[(p / 3) * DMODEL + d]
                      + ve[tok[n] * DMODEL + d];
}

// ---------------------------------------------------------------------------
// LayerNorm: one warp per row, fp32 in, bf16 out
// ---------------------------------------------------------------------------
__global__ void ln_k(const float* __restrict__ x, const float* __restrict__ s,
                     const float* __restrict__ b, bf16* __restrict__ y)
{
    int row  = blockIdx.x * 8 + (threadIdx.x >> 5);
    int lane = threadIdx.x & 31;
    const float4* xr = (const float4*)(x + (size_t)row * DMODEL);
    float4 v0 = xr[lane];
    float4 v1 = xr[lane + 32];

    float sum = v0.x + v0.y + v0.z + v0.w + v1.x + v1.y + v1.z + v1.w;
    #pragma unroll
    for (int o = 16; o > 0; o >>= 1) sum += __shfl_xor_sync(0xffffffffu, sum, o);
    float mu = sum * (1.0f / DMODEL);

    float d0x=v0.x-mu, d0y=v0.y-mu, d0z=v0.z-mu, d0w=v0.w-mu;
    float d1x=v1.x-mu, d1y=v1.y-mu, d1z=v1.z-mu, d1w=v1.w-mu;
    float sq = d0x*d0x+d0y*d0y+d0z*d0z+d0w*d0w + d1x*d1x+d1y*d1y+d1z*d1z+d1w*d1w;
    #pragma unroll
    for (int o = 16; o > 0; o >>= 1) sq += __shfl_xor_sync(0xffffffffu, sq, o);
    float rs = rsqrtf(sq * (1.0f / DMODEL) + 1e-5f);

    const float4* sv = (const float4*)s;
    const float4* bv = (const float4*)b;
    float4 s0 = sv[lane], s1 = sv[lane + 32];
    float4 b0 = bv[lane], b1 = bv[lane + 32];
    uint2 u0, u1;
    u0.x = pk2(d0x*rs*s0.x + b0.x, d0y*rs*s0.y + b0.y);
    u0.y = pk2(d0z*rs*s0.z + b0.z, d0w*rs*s0.w + b0.w);
    u1.x = pk2(d1x*rs*s1.x + b1.x, d1y*rs*s1.y + b1.y);
    u1.y = pk2(d1z*rs*s1.z + b1.z, d1w*rs*s1.w + b1.w);
    *(uint2*)(y + (size_t)row * DMODEL + lane * 4)        = u0;
    *(uint2*)(y + (size_t)row * DMODEL + (lane + 32) * 4) = u1;
}

// ---------------------------------------------------------------------------
// bf16 tensor-core attention (unchanged from R9)
// ---------------------------------------------------------------------------
__global__ __launch_bounds__(128)
void attn_k(const bf16* __restrict__ qkv, bf16* __restrict__ o)
{
    __shared__ bf16 sm[13824];
    __shared__ float zpart[4][96];
    __shared__ float zinv[96];

    int bh = blockIdx.x;
    int b = bh >> 3, h = bh & 7;
    int base = b * LSEQ;
    int tid  = threadIdx.x;
    int lane = tid & 31, wid = tid >> 5;
    int g = lane >> 2, lt = lane & 3;
    int ltile = lane >> 3, lr = lane & 7;
    int a_roff = (ltile & 1) * 8 + lr;
    int a_koff = (ltile >> 1) * 8;

    const bf16* Qg = qkv + (size_t)base * 768 + h * DKH;
    const bf16* Kg = Qg + DMODEL;
    const bf16* Vg = Qg + 2 * DMODEL;

    unsigned vreg[6][2];
    int d0 = 8 * wid;
    #pragma unroll
    for (int kc = 0; kc < 6; kc++) {
        int k0 = 16 * kc + 2 * lt;
        unsigned lo0 = *(const unsigned short*)(Vg + (size_t)k0       * 768 + d0 + g);
        unsigned hi0 = *(const unsigned short*)(Vg + (size_t)(k0 + 1) * 768 + d0 + g);
        unsigned lo1 = *(const unsigned short*)(Vg + (size_t)(k0 + 8) * 768 + d0 + g);
        unsigned hi1 = *(const unsigned short*)(Vg + (size_t)(k0 + 9) * 768 + d0 + g);
        vreg[kc][0] = lo0 | (hi0 << 16);
        vreg[kc][1] = lo1 | (hi1 << 16);
    }

    for (int idx = tid; idx < 96 * 4; idx += 128) {
        int r = idx >> 2, q = idx & 3;
        int kc = q >> 1, off8 = (q & 1) * 8;
        uint4 qv = *(const uint4*)(Qg + (size_t)r * 768 + q * 8);
        uint4 kv = *(const uint4*)(Kg + (size_t)r * 768 + q * 8);
        *(uint4*)&sm[kc * 2304 + r * 24 + off8] = qv;
        *(uint4*)&sm[4608 + kc * 2304 + r * 24 + off8] = kv;
    }
    __syncthreads();

    float acc[6][3][4];
    #pragma unroll
    for (int i = 0; i < 6; i++)
        #pragma unroll
        for (int j = 0; j < 3; j++)
            #pragma unroll
            for (int v = 0; v < 4; v++) acc[i][j][v] = 0.0f;

    int J0 = 3 * wid;
    #pragma unroll
    for (int kc = 0; kc < 2; kc++) {
        unsigned s0, s1, s2, s3, t0, t1, t2, t3;
        ldsm4(s0, s1, s2, s3,
              &sm[4608 + kc * 2304 + (24 * wid + a_roff) * 24 + a_koff]);
        ldsm4(t0, t1, t2, t3,
              &sm[4608 + kc * 2304 + (24 * wid + 16 + a_roff) * 24 + a_koff]);
        (void)t1; (void)t3;

        #pragma unroll
        for (int i = 0; i < 6; i++) {
            if (8 * J0 > 16 * i + 15) continue;
            unsigned a0, a1, a2, a3;
            ldsm4(a0, a1, a2, a3, &sm[kc * 2304 + (16 * i + a_roff) * 24 + a_koff]);
            if (8 * (J0 + 0) <= 16 * i + 15) mma_bf16(acc[i][0], a0, a1, a2, a3, s0, s2);
            if (8 * (J0 + 1) <= 16 * i + 15) mma_bf16(acc[i][1], a0, a1, a2, a3, s1, s3);
            if (8 * (J0 + 2) <= 16 * i + 15) mma_bf16(acc[i][2], a0, a1, a2, a3, t0, t2);
        }
    }
    __syncthreads();

    float zp[12];
    #pragma unroll
    for (int m = 0; m < 12; m++) zp[m] = 0.0f;
    const float invs = 0.17677669529663687f;

    #pragma unroll
    for (int i = 0; i < 6; i++) {
        int r0 = 16 * i + g, r1 = r0 + 8;
        #pragma unroll
        for (int jl = 0; jl < 3; jl++) {
            int J = J0 + jl;
            if (8 * J > 16 * i + 15) continue;
            int c = 8 * J + 2 * lt;
            float w0 = (c     <= r0) ? __expf(fminf(fmaxf(acc[i][jl][0] * invs, -5.0f), 5.0f)) : 0.0f;
            float w1 = (c + 1 <= r0) ? __expf(fminf(fmaxf(acc[i][jl][1] * invs, -5.0f), 5.0f)) : 0.0f;
            float w2 = (c     <= r1) ? __expf(fminf(fmaxf(acc[i][jl][2] * invs, -5.0f), 5.0f)) : 0.0f;
            float w3 = (c + 1 <= r1) ? __expf(fminf(fmaxf(acc[i][jl][3] * invs, -5.0f), 5.0f)) : 0.0f;
            zp[2 * i]     += w0 + w1;
            zp[2 * i + 1] += w2 + w3;
            int col = (J & 1) * 8 + 2 * lt;
            *(unsigned*)&sm[(J >> 1) * 2304 + r0 * 24 + col] = pk2(w0, w1);
            *(unsigned*)&sm[(J >> 1) * 2304 + r1 * 24 + col] = pk2(w2, w3);
        }
    }
    #pragma unroll
    for (int off = 1; off <= 2; off <<= 1)
        #pragma unroll
        for (int m = 0; m < 12; m++)
            zp[m] += __shfl_xor_sync(0xffffffffu, zp[m], off);
    if (lt == 0) {
        #pragma unroll
        for (int i = 0; i < 6; i++) {
            zpart[wid][16 * i + g]     = zp[2 * i];
            zpart[wid][16 * i + 8 + g] = zp[2 * i + 1];
        }
    }
    __syncthreads();
    if (tid < 96)
        zinv[tid] = 1.0f / (zpart[0][tid] + zpart[1][tid] + zpart[2][tid] + zpart[3][tid]);
    __syncthreads();

    float oacc[6][4];
    #pragma unroll
    for (int i = 0; i < 6; i++)
        #pragma unroll
        for (int v = 0; v < 4; v++) oacc[i][v] = 0.0f;

    #pragma unroll
    for (int i = 0; i < 6; i++) {
        #pragma unroll
        for (int kc = 0; kc < 6; kc++) {
            if (kc > i) break;
            unsigned a0, a1, a2, a3;
            ldsm4(a0, a1, a2, a3, &sm[kc * 2304 + (16 * i + a_roff) * 24 + a_koff]);
            mma_bf16(oacc[i], a0, a1, a2, a3, vreg[kc][0], vreg[kc][1]);
        }
    }

    #pragma unroll
    for (int i = 0; i < 6; i++) {
        int r0 = 16 * i + g, r1 = r0 + 8;
        float zi0 = zinv[r0], zi1 = zinv[r1];
        unsigned u0 = pk2(oacc[i][0] * zi0, oacc[i][1] * zi0);
        unsigned u1 = pk2(oacc[i][2] * zi1, oacc[i][3] * zi1);
        *(unsigned*)(o + (size_t)(base + r0) * DMODEL + h * DKH + d0 + 2 * lt) = u0;
        *(unsigned*)(o + (size_t)(base + r1) * DMODEL + h * DKH + d0 + 2 * lt) = u1;
    }
}

// ---------------------------------------------------------------------------
// bf16 GEMM, KT=32, 3-stage cp.async ring (wait_group 1), dynamic smem.
// BM x 128 tile. OP: 0 bias, 1 bias+relu, 2 bias+residual.
// OUTM bit0: fp32 C; bit1: bf16 Cb.
// smem layout: As[3][BM][40] then Bs[3][32][136] (bf16 elems)
// ---------------------------------------------------------------------------
#define AST 40
#define BST 136

template<int BM, int OP, int OUTM>
__global__ __launch_bounds__(256)
void hgemm_k(const bf16* __restrict__ A, const bf16* __restrict__ B,
             const float* __restrict__ bias, const float* __restrict__ res,
             float* __restrict__ C, bf16* __restrict__ Cb,
             int M, int N, int K)
{
    extern __shared__ bf16 dsm[];
    constexpr int ASZ = BM * AST;
    constexpr int BSZ = 32 * BST;
    bf16* As = dsm;
    bf16* Bs = dsm + 3 * ASZ;

    constexpr int MW = (BM == 128) ? 4 : 2;
    constexpr int WN = 128 / (8 / MW);
    constexpr int MI = (BM / MW) / 16;
    constexpr int NJ = WN / 8;

    int tid  = threadIdx.x;
    int lane = tid & 31, wid = tid >> 5;
    int g = lane >> 2, lt = lane & 3;
    int wm = (wid % MW) * (BM / MW);
    int wn = (wid / MW) * WN;
    int m0 = blockIdx.y * BM;
    int n0 = blockIdx.x * 128;

    int ltile = lane >> 3, lr = lane & 7;
    int a_roff = (ltile & 1) * 8 + lr;
    int a_koff = (ltile >> 1) * 8;
    int b_roff = (ltile & 1) * 8 + lr;
    int b_coff = (ltile >> 1) * 8;

    float acc[MI][NJ][4];
    #pragma unroll
    for (int i = 0; i < MI; i++)
        #pragma unroll
        for (int j = 0; j < NJ; j++)
            #pragma unroll
            for (int v = 0; v < 4; v++) acc[i][j][v] = 0.0f;

    int T = K >> 5;

    auto issue = [&](int buf, int kt) {
        int k0 = kt * 32;
        bf16* Ab = As + buf * ASZ;
        bf16* Bb = Bs + buf * BSZ;
        if (BM == 128) {
            int row = tid >> 1, c0 = (tid & 1) * 8;
            const bf16* src = A + (size_t)(m0 + row) * K + k0;
            cpa16(Ab + row * AST + c0,      src + c0);
            cpa16(Ab + row * AST + c0 + 16, src + c0 + 16);
        } else {
            int row = tid >> 2, c0 = (tid & 3) * 8;
            cpa16(Ab + row * AST + c0, A + (size_t)(m0 + row) * K + k0 + c0);
        }
        int brow = tid >> 4, bc8 = (tid & 15) * 8;
        cpa16(Bb + brow * BST + bc8,        B + (size_t)(k0 + brow) * N + n0 + bc8);
        cpa16(Bb + (brow + 16) * BST + bc8, B + (size_t)(k0 + 16 + brow) * N + n0 + bc8);
    };

    issue(0, 0); cpa_commit();
    issue(1, 1); cpa_commit();

    int buf = 0;
    for (int kt = 0; kt < T; kt++) {
        cpa_wait1();
        __syncthreads();
        if (kt + 2 < T) issue((kt + 2) % 3, kt + 2);
        cpa_commit();

        bf16* Ab = As + buf * ASZ;
        bf16* Bb = Bs + buf * BSZ;
        #pragma unroll
        for (int kk = 0; kk < 32; kk += 16) {
            unsigned af[MI][4], bf[NJ][2];
            #pragma unroll
            for (int i = 0; i < MI; i++)
                ldsm4(af[i][0], af[i][1], af[i][2], af[i][3],
                      Ab + (wm + 16 * i + a_roff) * AST + kk + a_koff);
            #pragma unroll
            for (int jp = 0; jp < NJ / 2; jp++) {
                unsigned r0, r1, r2, r3;
                ldsm4t(r0, r1, r2, r3,
                       Bb + (kk + b_roff) * BST + wn + 16 * jp + b_coff);
                bf[2 * jp][0] = r0;  bf[2 * jp][1] = r1;
                bf[2 * jp + 1][0] = r2;  bf[2 * jp + 1][1] = r3;
            }
            #pragma unroll
            for (int i = 0; i < MI; i++)
                #pragma unroll
                for (int j = 0; j < NJ; j++)
                    mma_bf16(acc[i][j], af[i][0], af[i][1], af[i][2], af[i][3],
                             bf[j][0], bf[j][1]);
        }
        buf = (buf + 1 == 3) ? 0 : buf + 1;
    }

    // epilogue
    #pragma unroll
    for (int i = 0; i < MI; i++) {
        int r0 = m0 + wm + 16 * i + g;
        #pragma unroll
        for (int j = 0; j < NJ; j++) {
            int c = n0 + wn + 8 * j + 2 * lt;
            float bx = bias[c], by = bias[c + 1];
            float2 v0, v1;
            v0.x = acc[i][j][0] + bx;  v0.y = acc[i][j][1] + by;
            v1.x = acc[i][j][2] + bx;  v1.y = acc[i][j][3] + by;
            if (OP == 1) {
                v0.x = fmaxf(v0.x, 0.0f); v0.y = fmaxf(v0.y, 0.0f);
                v1.x = fmaxf(v1.x, 0.0f); v1.y = fmaxf(v1.y, 0.0f);
            }
            if (OP == 2) {
                float2 r0v = *(const float2*)(res + (size_t)r0 * N + c);
                float2 r1v = *(const float2*)(res + (size_t)(r0 + 8) * N + c);
                v0.x += r0v.x; v0.y += r0v.y;
                v1.x += r1v.x; v1.y += r1v.y;
            }
            if (OUTM & 1) {
                *(float2*)(C + (size_t)r0 * N + c) = v0;
                *(float2*)(C + (size_t)(r0 + 8) * N + c) = v1;
            }
            if (OUTM & 2) {
                *(unsigned*)(Cb + (size_t)r0 * N + c) = pk2(v0.x, v0.y);
                *(unsigned*)(Cb + (size_t)(r0 + 8) * N + c) = pk2(v1.x, v1.y);
            }
        }
    }
}

#define SMEM128 ((3 * 128 * AST + 3 * 32 * BST) * 2)
#define SMEM64  ((3 * 64 * AST + 3 * 32 * BST) * 2)

// ---------------------------------------------------------------------------
// In-place log_softmax over VOCAB=1024
// ---------------------------------------------------------------------------
__global__ void lsm_k(float* __restrict__ out)
{
    __shared__ float red[256];
    int n = blockIdx.x, t = threadIdx.x;
    float v[4];
    #pragma unroll
    for (int j = 0; j < 4; j++) v[j] = out[(size_t)n * NVOCAB + t + j * 256];

    float m = fmaxf(fmaxf(v[0], v[1]), fmaxf(v[2], v[3]));
    red[t] = m;
    __syncthreads();
    #pragma unroll
    for (int o = 128; o > 0; o >>= 1) {
        if (t < o) red[t] = fmaxf(red[t], red[t + o]);
        __syncthreads();
    }
    float M = red[0];
    __syncthreads();

    float s = 0.0f;
    #pragma unroll
    for (int j = 0; j < 4; j++) s += __expf(v[j] - M);
    red[t] = s;
    __syncthreads();
    #pragma unroll
    for (int o = 128; o > 0; o >>= 1) {
        if (t < o) red[t] += red[t + o];
        __syncthreads();
    }
    float lse = M + __logf(red[0]);

    #pragma unroll
    for (int j = 0; j < 4; j++)
        out[(size_t)n * NVOCAB + t + j * 256] = v[j] - lse;
}

// ---------------------------------------------------------------------------
// Launch
// ---------------------------------------------------------------------------
extern "C" void kernel_launch(void* const* d_in, const int* in_sizes, int n_in,
                              void* d_out, int out_size)
{
    const int*   tokens    = (const int*)  d_in[0];
    const int*   pos_idx   = (const int*)  d_in[1];
    const float* value_emb = (const float*)d_in[4];
    const float* coord_emb = (const float*)d_in[5];
    const float* pos_emb   = (const float*)d_in[6];
    const float* ln1_s     = (const float*)d_in[7];
    const float* ln1_b     = (const float*)d_in[8];
    const float* W_qkv     = (const float*)d_in[9];
    const float* b_qkv     = (const float*)d_in[10];
    const float* W_o       = (const float*)d_in[11];
    const float* b_o       = (const float*)d_in[12];
    const float* ln2_s     = (const float*)d_in[13];
    const float* ln2_b     = (const float*)d_in[14];
    const float* W_ff1     = (const float*)d_in[15];
    const float* b_ff1     = (const float*)d_in[16];
    const float* W_ff2     = (const float*)d_in[17];
    const float* b_ff2     = (const float*)d_in[18];
    const float* W_gen     = (const float*)d_in[19];
    const float* b_gen     = (const float*)d_in[20];
    float* out = (float*)d_out;

    float *x;
    bf16 *qkvb, *xn, *att, *mid, *xb;
    bf16 *wqkvb, *wob, *wf1b, *wf2b, *wgenb;
    cudaGetSymbolAddress((void**)&x,    g_x);
    cudaGetSymbolAddress((void**)&qkvb, g_qkvb);
    cudaGetSymbolAddress((void**)&xn,   g_xn);
    cudaGetSymbolAddress((void**)&att,  g_att);
    cudaGetSymbolAddress((void**)&mid,  g_mid);
    cudaGetSymbolAddress((void**)&xb,   g_xb);
    cudaGetSymbolAddress((void**)&wqkvb, g_wqkv);
    cudaGetSymbolAddress((void**)&wob,   g_wo);
    cudaGetSymbolAddress((void**)&wf1b,  g_wf1);
    cudaGetSymbolAddress((void**)&wf2b,  g_wf2);
    cudaGetSymbolAddress((void**)&wgenb, g_wgen);

    cudaFuncSetAttribute(hgemm_k<128, 0, 2>, cudaFuncAttributeMaxDynamicSharedMemorySize, SMEM128);
    cudaFuncSetAttribute(hgemm_k<128, 1, 2>, cudaFuncAttributeMaxDynamicSharedMemorySize, SMEM128);
    cudaFuncSetAttribute(hgemm_k<128, 0, 1>, cudaFuncAttributeMaxDynamicSharedMemorySize, SMEM128);
    cudaFuncSetAttribute(hgemm_k<64, 2, 1>,  cudaFuncAttributeMaxDynamicSharedMemorySize, SMEM64);
    cudaFuncSetAttribute(hgemm_k<64, 2, 3>,  cudaFuncAttributeMaxDynamicSharedMemorySize, SMEM64);

    cvt5_k<<<1792, 256>>>((const float4*)W_qkv, (const float4*)W_o,
                          (const float4*)W_ff1, (const float4*)W_ff2,
                          (const float4*)W_gen,
                          (uint2*)wqkvb, (uint2*)wob, (uint2*)wf1b,
                          (uint2*)wf2b, (uint2*)wgenb);

    embed_k<<<NTOK, DMODEL>>>(tokens, pos_idx, value_emb, coord_emb, pos_emb, x);

    for (int l = 0; l < NLAYER; l++) {
        const bf16* wqkv = wqkvb + (size_t)l * DMODEL * 3 * DMODEL;
        const float* bqkv = b_qkv + (size_t)l * 3 * DMODEL;
        const bf16* wo    = wob   + (size_t)l * DMODEL * DMODEL;
        const float* bo   = b_o   + (size_t)l * DMODEL;
        const bf16* wf1   = wf1b  + (size_t)l * DMODEL * 4 * DMODEL;
        const float* bf1  = b_ff1 + (size_t)l * 4 * DMODEL;
        const bf16* wf2   = wf2b  + (size_t)l * 4 * DMODEL * DMODEL;
        const float* bf2  = b_ff2 + (size_t)l * DMODEL;

        ln_k<<<NTOK / 8, 256>>>(x, ln1_s + l * DMODEL, ln1_b + l * DMODEL, xn);

        { dim3 g(3 * DMODEL / 128, NTOK / 128);
          hgemm_k<128, 0, 2><<<g, 256, SMEM128>>>(xn, wqkv, bqkv, nullptr, nullptr, qkvb,
                                                  NTOK, 3 * DMODEL, DMODEL); }

        attn_k<<<NBATCH * NHEAD, 128>>>(qkvb, att);

        { dim3 g(DMODEL / 128, NTOK / 64);
          hgemm_k<64, 2, 1><<<g, 256, SMEM64>>>(att, wo, bo, x, x, nullptr,
                                                NTOK, DMODEL, DMODEL); }

        ln_k<<<NTOK / 8, 256>>>(x, ln2_s + l * DMODEL, ln2_b + l * DMODEL, xn);

        { dim3 g(4 * DMODEL / 128, NTOK / 128);
          hgemm_k<128, 1, 2><<<g, 256, SMEM128>>>(xn, wf1, bf1, nullptr, nullptr, mid,
                                                  NTOK, 4 * DMODEL, DMODEL); }

        { dim3 g(DMODEL / 128, NTOK / 64);
          hgemm_k<64, 2, 3><<<g, 256, SMEM64>>>(mid, wf2, bf2, x, x, xb,
                                                NTOK, DMODEL, 4 * DMODEL); }
    }

    { dim3 g(NVOCAB / 128, NTOK / 128);
      hgemm_k<128, 0, 1><<<g, 256, SMEM128>>>(xb, wgenb, b_gen, nullptr, out, nullptr,
                                              NTOK, NVOCAB, DMODEL); }

    lsm_k<<<NTOK, 256>>>(out);
}

// round 12
// speedup vs baseline: 1.0203x; 1.0203x over previous
#include <cuda_runtime.h>
#include <cuda_bf16.h>
#include <cstdint>
#include <math.h>

#define NTOK 6144
#define DMODEL 256
#define NHEAD 8
#define DKH 32
#define NLAYER 2
#define NVOCAB 1024
#define LSEQ 96
#define NBATCH 64

typedef __nv_bfloat16 bf16;
typedef __nv_bfloat162 bf162;

// ---------------------------------------------------------------------------
// Scratch
// ---------------------------------------------------------------------------
__device__ float g_x  [NTOK * DMODEL];
__device__ bf16  g_qkvb[NTOK * 3 * DMODEL];
__device__ bf16  g_xn [NTOK * DMODEL];
__device__ bf16  g_att[NTOK * DMODEL];
__device__ bf16  g_mid[NTOK * 4 * DMODEL];
__device__ bf16  g_xb [NTOK * DMODEL];
__device__ bf16 g_wqkv[NLAYER * DMODEL * 3 * DMODEL];
__device__ bf16 g_wo  [NLAYER * DMODEL * DMODEL];
__device__ bf16 g_wf1 [NLAYER * DMODEL * 4 * DMODEL];
__device__ bf16 g_wf2 [NLAYER * 4 * DMODEL * DMODEL];
__device__ bf16 g_wgen[DMODEL * NVOCAB];

// ---------------------------------------------------------------------------
// helpers
// ---------------------------------------------------------------------------
__device__ __forceinline__ unsigned pk2(float a, float b)
{
    bf162 t = __floats2bfloat162_rn(a, b);
    return *(unsigned*)&t;
}

__device__ __forceinline__ void mma_bf16(float* c, unsigned a0, unsigned a1,
                                         unsigned a2, unsigned a3,
                                         unsigned b0, unsigned b1)
{
    asm volatile(
        "mma.sync.aligned.m16n8k16.row.col.f32.bf16.bf16.f32 "
        "{%0,%1,%2,%3}, {%4,%5,%6,%7}, {%8,%9}, {%0,%1,%2,%3};"
        : "+f"(c[0]), "+f"(c[1]), "+f"(c[2]), "+f"(c[3])
        : "r"(a0), "r"(a1), "r"(a2), "r"(a3), "r"(b0), "r"(b1));
}

__device__ __forceinline__ void ldsm4(unsigned& r0, unsigned& r1,
                                      unsigned& r2, unsigned& r3, const void* p)
{
    unsigned a = (unsigned)__cvta_generic_to_shared(p);
    asm volatile("ldmatrix.sync.aligned.m8n8.x4.shared.b16 {%0,%1,%2,%3}, [%4];"
                 : "=r"(r0), "=r"(r1), "=r"(r2), "=r"(r3) : "r"(a));
}

__device__ __forceinline__ void ldsm4t(unsigned& r0, unsigned& r1,
                                       unsigned& r2, unsigned& r3, const void* p)
{
    unsigned a = (unsigned)__cvta_generic_to_shared(p);
    asm volatile("ldmatrix.sync.aligned.m8n8.x4.trans.shared.b16 {%0,%1,%2,%3}, [%4];"
                 : "=r"(r0), "=r"(r1), "=r"(r2), "=r"(r3) : "r"(a));
}

__device__ __forceinline__ void cpa16(void* smem_dst, const void* gsrc)
{
    unsigned s = (unsigned)__cvta_generic_to_shared(smem_dst);
    asm volatile("cp.async.cg.shared.global [%0], [%1], 16;\n" :: "r"(s), "l"(gsrc));
}
__device__ __forceinline__ void cpa_commit()
{
    asm volatile("cp.async.commit_group;\n" ::: "memory");
}
__device__ __forceinline__ void cpa_wait2()
{
    asm volatile("cp.async.wait_group 2;\n" ::: "memory");
}

// ---------------------------------------------------------------------------
// Fused fp32->bf16 conversion of all 5 weight tensors (one launch)
// ---------------------------------------------------------------------------
__global__ void cvt5_k(const float4* __restrict__ q,  const float4* __restrict__ o,
                       const float4* __restrict__ f1, const float4* __restrict__ f2,
                       const float4* __restrict__ gw,
                       uint2* __restrict__ qd,  uint2* __restrict__ od,
                       uint2* __restrict__ f1d, uint2* __restrict__ f2d,
                       uint2* __restrict__ gd)
{
    int i = blockIdx.x * 256 + threadIdx.x;
    const float4* s; uint2* d; int j = i;
    if (j < 98304)                    { s = q;  d = qd;  }
    else if ((j -= 98304)  < 32768)   { s = o;  d = od;  }
    else if ((j -= 32768)  < 131072)  { s = f1; d = f1d; }
    else if ((j -= 131072) < 131072)  { s = f2; d = f2d; }
    else { j -= 131072;                 s = gw; d = gd;  }
    float4 v = s[j];
    uint2 u;
    u.x = pk2(v.x, v.y);
    u.y = pk2(v.z, v.w);
    d[j] = u;
}

// ---------------------------------------------------------------------------
// Embedding
// ---------------------------------------------------------------------------
__global__ void embed_k(const int* __restrict__ tok, const int* __restrict__ pos,
                        const float* __restrict__ ve, const float* __restrict__ ce,
                        const float* __restrict__ pe, float* __restrict__ x)
{
    int n = blockIdx.x;
    int d = threadIdx.x;
    int p = pos[n];
    x[n * DMODEL + d] = ce[(p % 3) * DMODEL + d]
                      + pe[(p / 3) * DMODEL + d]
                      + ve[tok[n] * DMODEL + d];
}

// ---------------------------------------------------------------------------
// LayerNorm: one warp per row, fp32 in, bf16 out
// ---------------------------------------------------------------------------
__global__ void ln_k(const float* __restrict__ x, const float* __restrict__ s,
                     const float* __restrict__ b, bf16* __restrict__ y)
{
    int row  = blockIdx.x * 8 + (threadIdx.x >> 5);
    int lane = threadIdx.x & 31;
    const float4* xr = (const float4*)(x + (size_t)row * DMODEL);
    float4 v0 = xr[lane];
    float4 v1 = xr[lane + 32];

    float sum = v0.x + v0.y + v0.z + v0.w + v1.x + v1.y + v1.z + v1.w;
    #pragma unroll
    for (int o = 16; o > 0; o >>= 1) sum += __shfl_xor_sync(0xffffffffu, sum, o);
    float mu = sum * (1.0f / DMODEL);

    float d0x=v0.x-mu, d0y=v0.y-mu, d0z=v0.z-mu, d0w=v0.w-mu;
    float d1x=v1.x-mu, d1y=v1.y-mu, d1z=v1.z-mu, d1w=v1.w-mu;
    float sq = d0x*d0x+d0y*d0y+d0z*d0z+d0w*d0w + d1x*d1x+d1y*d1y+d1z*d1z+d1w*d1w;
    #pragma unroll
    for (int o = 16; o > 0; o >>= 1) sq += __shfl_xor_sync(0xffffffffu, sq, o);
    float rs = rsqrtf(sq * (1.0f / DMODEL) + 1e-5f);

    const float4* sv = (const float4*)s;
    const float4* bv = (const float4*)b;
    float4 s0 = sv[lane], s1 = sv[lane + 32];
    float4 b0 = bv[lane], b1 = bv[lane + 32];
    uint2 u0, u1;
    u0.x = pk2(d0x*rs*s0.x + b0.x, d0y*rs*s0.y + b0.y);
    u0.y = pk2(d0z*rs*s0.z + b0.z, d0w*rs*s0.w + b0.w);
    u1.x = pk2(d1x*rs*s1.x + b1.x, d1y*rs*s1.y + b1.y);
    u1.y = pk2(d1z*rs*s1.z + b1.z, d1w*rs*s1.w + b1.w);
    *(uint2*)(y + (size_t)row * DMODEL + lane * 4)        = u0;
    *(uint2*)(y + (size_t)row * DMODEL + (lane + 32) * 4) = u1;
}

// ---------------------------------------------------------------------------
// bf16 tensor-core attention (unchanged from R9)
// ---------------------------------------------------------------------------
__global__ __launch_bounds__(128)
void attn_k(const bf16* __restrict__ qkv, bf16* __restrict__ o)
{
    __shared__ bf16 sm[13824];
    __shared__ float zpart[4][96];
    __shared__ float zinv[96];

    int bh = blockIdx.x;
    int b = bh >> 3, h = bh & 7;
    int base = b * LSEQ;
    int tid  = threadIdx.x;
    int lane = tid & 31, wid = tid >> 5;
    int g = lane >> 2, lt = lane & 3;
    int ltile = lane >> 3, lr = lane & 7;
    int a_roff = (ltile & 1) * 8 + lr;
    int a_koff = (ltile >> 1) * 8;

    const bf16* Qg = qkv + (size_t)base * 768 + h * DKH;
    const bf16* Kg = Qg + DMODEL;
    const bf16* Vg = Qg + 2 * DMODEL;

    unsigned vreg[6][2];
    int d0 = 8 * wid;
    #pragma unroll
    for (int kc = 0; kc < 6; kc++) {
        int k0 = 16 * kc + 2 * lt;
        unsigned lo0 = *(const unsigned short*)(Vg + (size_t)k0       * 768 + d0 + g);
        unsigned hi0 = *(const unsigned short*)(Vg + (size_t)(k0 + 1) * 768 + d0 + g);
        unsigned lo1 = *(const unsigned short*)(Vg + (size_t)(k0 + 8) * 768 + d0 + g);
        unsigned hi1 = *(const unsigned short*)(Vg + (size_t)(k0 + 9) * 768 + d0 + g);
        vreg[kc][0] = lo0 | (hi0 << 16);
        vreg[kc][1] = lo1 | (hi1 << 16);
    }

    for (int idx = tid; idx < 96 * 4; idx += 128) {
        int r = idx >> 2, q = idx & 3;
        int kc = q >> 1, off8 = (q & 1) * 8;
        uint4 qv = *(const uint4*)(Qg + (size_t)r * 768 + q * 8);
        uint4 kv = *(const uint4*)(Kg + (size_t)r * 768 + q * 8);
        *(uint4*)&sm[kc * 2304 + r * 24 + off8] = qv;
        *(uint4*)&sm[4608 + kc * 2304 + r * 24 + off8] = kv;
    }
    __syncthreads();

    float acc[6][3][4];
    #pragma unroll
    for (int i = 0; i < 6; i++)
        #pragma unroll
        for (int j = 0; j < 3; j++)
            #pragma unroll
            for (int v = 0; v < 4; v++) acc[i][j][v] = 0.0f;

    int J0 = 3 * wid;
    #pragma unroll
    for (int kc = 0; kc < 2; kc++) {
        unsigned s0, s1, s2, s3, t0, t1, t2, t3;
        ldsm4(s0, s1, s2, s3,
              &sm[4608 + kc * 2304 + (24 * wid + a_roff) * 24 + a_koff]);
        ldsm4(t0, t1, t2, t3,
              &sm[4608 + kc * 2304 + (24 * wid + 16 + a_roff) * 24 + a_koff]);
        (void)t1; (void)t3;

        #pragma unroll
        for (int i = 0; i < 6; i++) {
            if (8 * J0 > 16 * i + 15) continue;
            unsigned a0, a1, a2, a3;
            ldsm4(a0, a1, a2, a3, &sm[kc * 2304 + (16 * i + a_roff) * 24 + a_koff]);
            if (8 * (J0 + 0) <= 16 * i + 15) mma_bf16(acc[i][0], a0, a1, a2, a3, s0, s2);
            if (8 * (J0 + 1) <= 16 * i + 15) mma_bf16(acc[i][1], a0, a1, a2, a3, s1, s3);
            if (8 * (J0 + 2) <= 16 * i + 15) mma_bf16(acc[i][2], a0, a1, a2, a3, t0, t2);
        }
    }
    __syncthreads();

    float zp[12];
    #pragma unroll
    for (int m = 0; m < 12; m++) zp[m] = 0.0f;
    const float invs = 0.17677669529663687f;

    #pragma unroll
    for (int i = 0; i < 6; i++) {
        int r0 = 16 * i + g, r1 = r0 + 8;
        #pragma unroll
        for (int jl = 0; jl < 3; jl++) {
            int J = J0 + jl;
            if (8 * J > 16 * i + 15) continue;
            int c = 8 * J + 2 * lt;
            float w0 = (c     <= r0) ? __expf(fminf(fmaxf(acc[i][jl][0] * invs, -5.0f), 5.0f)) : 0.0f;
            float w1 = (c + 1 <= r0) ? __expf(fminf(fmaxf(acc[i][jl][1] * invs, -5.0f), 5.0f)) : 0.0f;
            float w2 = (c     <= r1) ? __expf(fminf(fmaxf(acc[i][jl][2] * invs, -5.0f), 5.0f)) : 0.0f;
            float w3 = (c + 1 <= r1) ? __expf(fminf(fmaxf(acc[i][jl][3] * invs, -5.0f), 5.0f)) : 0.0f;
            zp[2 * i]     += w0 + w1;
            zp[2 * i + 1] += w2 + w3;
            int col = (J & 1) * 8 + 2 * lt;
            *(unsigned*)&sm[(J >> 1) * 2304 + r0 * 24 + col] = pk2(w0, w1);
            *(unsigned*)&sm[(J >> 1) * 2304 + r1 * 24 + col] = pk2(w2, w3);
        }
    }
    #pragma unroll
    for (int off = 1; off <= 2; off <<= 1)
        #pragma unroll
        for (int m = 0; m < 12; m++)
            zp[m] += __shfl_xor_sync(0xffffffffu, zp[m], off);
    if (lt == 0) {
        #pragma unroll
        for (int i = 0; i < 6; i++) {
            zpart[wid][16 * i + g]     = zp[2 * i];
            zpart[wid][16 * i + 8 + g] = zp[2 * i + 1];
        }
    }
    __syncthreads();
    if (tid < 96)
        zinv[tid] = 1.0f / (zpart[0][tid] + zpart[1][tid] + zpart[2][tid] + zpart[3][tid]);
    __syncthreads();

    float oacc[6][4];
    #pragma unroll
    for (int i = 0; i < 6; i++)
        #pragma unroll
        for (int v = 0; v < 4; v++) oacc[i][v] = 0.0f;

    #pragma unroll
    for (int i = 0; i < 6; i++) {
        #pragma unroll
        for (int kc = 0; kc < 6; kc++) {
            if (kc > i) break;
            unsigned a0, a1, a2, a3;
            ldsm4(a0, a1, a2, a3, &sm[kc * 2304 + (16 * i + a_roff) * 24 + a_koff]);
            mma_bf16(oacc[i], a0, a1, a2, a3, vreg[kc][0], vreg[kc][1]);
        }
    }

    #pragma unroll
    for (int i = 0; i < 6; i++) {
        int r0 = 16 * i + g, r1 = r0 + 8;
        float zi0 = zinv[r0], zi1 = zinv[r1];
        unsigned u0 = pk2(oacc[i][0] * zi0, oacc[i][1] * zi0);
        unsigned u1 = pk2(oacc[i][2] * zi1, oacc[i][3] * zi1);
        *(unsigned*)(o + (size_t)(base + r0) * DMODEL + h * DKH + d0 + 2 * lt) = u0;
        *(unsigned*)(o + (size_t)(base + r1) * DMODEL + h * DKH + d0 + 2 * lt) = u1;
    }
}

// ---------------------------------------------------------------------------
// bf16 GEMM, 128x128 tile, 4 warps (128 thr), warp tile 64x64 (CUTLASS shape).
// KT=16, 4-stage cp.async ring (wait_group 2), static smem.
// Per warp per iter: 4 ldsm4 + 4 ldsm4t -> 32 mma.
// OP: 0 bias, 1 bias+relu. OUTM bit0: fp32 C; bit1: bf16 Cb.
// ---------------------------------------------------------------------------
template<int OP, int OUTM>
__global__ __launch_bounds__(128)
void hg128_k(const bf16* __restrict__ A, const bf16* __restrict__ B,
             const float* __restrict__ bias, const float* __restrict__ res,
             float* __restrict__ C, bf16* __restrict__ Cb,
             int M, int N, int K)
{
    __shared__ bf16 As[4][128][24];
    __shared__ bf16 Bs[4][16][136];

    int tid  = threadIdx.x;
    int lane = tid & 31, wid = tid >> 5;
    int g = lane >> 2, lt = lane & 3;
    int wm = (wid & 1) * 64;
    int wn = (wid >> 1) * 64;
    int m0 = blockIdx.y * 128;
    int n0 = blockIdx.x * 128;

    int ltile = lane >> 3, lr = lane & 7;
    int a_roff = (ltile & 1) * 8 + lr;
    int a_koff = (ltile >> 1) * 8;
    int b_roff = (ltile & 1) * 8 + lr;
    int b_coff = (ltile >> 1) * 8;

    float acc[4][8][4];
    #pragma unroll
    for (int i = 0; i < 4; i++)
        #pragma unroll
        for (int j = 0; j < 8; j++)
            #pragma unroll
            for (int v = 0; v < 4; v++) acc[i][j][v] = 0.0f;

    int T = K >> 4;

    auto issue = [&](int buf, int kt) {
        int k0 = kt * 16;
        const bf16* asrc = A + (size_t)(m0 + tid) * K + k0;
        cpa16(&As[buf][tid][0], asrc);
        cpa16(&As[buf][tid][8], asrc + 8);
        #pragma unroll
        for (int jj = 0; jj < 2; jj++) {
            int idx = tid + jj * 128;
            int row = idx >> 4, c8 = (idx & 15) * 8;
            cpa16(&Bs[buf][row][c8], B + (size_t)(k0 + row) * N + n0 + c8);
        }
    };

    issue(0, 0); cpa_commit();
    issue(1, 1); cpa_commit();
    issue(2, 2); cpa_commit();

    for (int kt = 0; kt < T; kt++) {
        cpa_wait2();
        __syncthreads();
        if (kt + 3 < T) issue((kt + 3) & 3, kt + 3);
        cpa_commit();

        int buf = kt & 3;
        unsigned af[4][4], bf[8][2];
        #pragma unroll
        for (int i = 0; i < 4; i++)
            ldsm4(af[i][0], af[i][1], af[i][2], af[i][3],
                  &As[buf][wm + 16 * i + a_roff][a_koff]);
        #pragma unroll
        for (int jp = 0; jp < 4; jp++) {
            unsigned r0, r1, r2, r3;
            ldsm4t(r0, r1, r2, r3, &Bs[buf][b_roff][wn + 16 * jp + b_coff]);
            bf[2 * jp][0] = r0;  bf[2 * jp][1] = r1;
            bf[2 * jp + 1][0] = r2;  bf[2 * jp + 1][1] = r3;
        }
        #pragma unroll
        for (int i = 0; i < 4; i++)
            #pragma unroll
            for (int j = 0; j < 8; j++)
                mma_bf16(acc[i][j], af[i][0], af[i][1], af[i][2], af[i][3],
                         bf[j][0], bf[j][1]);
    }

    // epilogue
    #pragma unroll
    for (int i = 0; i < 4; i++) {
        int r0 = m0 + wm + 16 * i + g;
        #pragma unroll
        for (int j = 0; j < 8; j++) {
            int c = n0 + wn + 8 * j + 2 * lt;
            float bx = bias[c], by = bias[c + 1];
            float2 v0, v1;
            v0.x = acc[i][j][0] + bx;  v0.y = acc[i][j][1] + by;
            v1.x = acc[i][j][2] + bx;  v1.y = acc[i][j][3] + by;
            if (OP == 1) {
                v0.x = fmaxf(v0.x, 0.0f); v0.y = fmaxf(v0.y, 0.0f);
                v1.x = fmaxf(v1.x, 0.0f); v1.y = fmaxf(v1.y, 0.0f);
            }
            if (OUTM & 1) {
                *(float2*)(C + (size_t)r0 * N + c) = v0;
                *(float2*)(C + (size_t)(r0 + 8) * N + c) = v1;
            }
            if (OUTM & 2) {
                *(unsigned*)(Cb + (size_t)r0 * N + c) = pk2(v0.x, v0.y);
                *(unsigned*)(Cb + (size_t)(r0 + 8) * N + c) = pk2(v1.x, v1.y);
            }
        }
    }
}

// ---------------------------------------------------------------------------
// bf16 GEMM, BM=64 x 128 tile, 256 thr, KT=16, 4-stage ring (R9 proven).
// OP 2: bias+residual. OUTM bit0: fp32 C; bit1: bf16 Cb.
// ---------------------------------------------------------------------------
template<int OP, int OUTM>
__global__ __launch_bounds__(256, 2)
void hg64_k(const bf16* __restrict__ A, const bf16* __restrict__ B,
            const float* __restrict__ bias, const float* __restrict__ res,
            float* __restrict__ C, bf16* __restrict__ Cb,
            int M, int N, int K)
{
    constexpr int BM = 64;
    __shared__ bf16 As[4][BM][24];
    __shared__ bf16 Bs[4][16][136];

    constexpr int MW = 2;
    constexpr int WN = 32;
    constexpr int MI = 2;
    constexpr int NJ = 4;

    int tid  = threadIdx.x;
    int lane = tid & 31, wid = tid >> 5;
    int g = lane >> 2, lt = lane & 3;
    int wm = (wid % MW) * 32;
    int wn = (wid / MW) * WN;
    int m0 = blockIdx.y * BM;
    int n0 = blockIdx.x * 128;

    int ar   = tid >> 1;
    int ah   = (tid & 1) * 8;
    int brow = tid >> 4;
    int bc8  = (tid & 15) * 8;

    int ltile = lane >> 3, lr = lane & 7;
    int a_roff = (ltile & 1) * 8 + lr;
    int a_koff = (ltile >> 1) * 8;
    int b_roff = (ltile & 1) * 8 + lr;
    int b_coff = (ltile >> 1) * 8;

    float acc[MI][NJ][4];
    #pragma unroll
    for (int i = 0; i < MI; i++)
        #pragma unroll
        for (int j = 0; j < NJ; j++)
            #pragma unroll
            for (int v = 0; v < 4; v++) acc[i][j][v] = 0.0f;

    int T = K >> 4;

    auto issue = [&](int buf, int kt) {
        int k0 = kt * 16;
        if (tid < 128)
            cpa16(&As[buf][ar][ah], A + (size_t)(m0 + ar) * K + k0 + ah);
        cpa16(&Bs[buf][brow][bc8], B + (size_t)(k0 + brow) * N + n0 + bc8);
    };

    issue(0, 0); cpa_commit();
    issue(1, 1); cpa_commit();
    issue(2, 2); cpa_commit();

    for (int kt = 0; kt < T; kt++) {
        cpa_wait2();
        __syncthreads();
        if (kt + 3 < T) issue((kt + 3) & 3, kt + 3);
        cpa_commit();

        int buf = kt & 3;
        unsigned af[MI][4], bf[NJ][2];
        #pragma unroll
        for (int i = 0; i < MI; i++)
            ldsm4(af[i][0], af[i][1], af[i][2], af[i][3],
                  &As[buf][wm + 16 * i + a_roff][a_koff]);
        #pragma unroll
        for (int jp = 0; jp < NJ / 2; jp++) {
            unsigned r0, r1, r2, r3;
            ldsm4t(r0, r1, r2, r3, &Bs[buf][b_roff][wn + 16 * jp + b_coff]);
            bf[2 * jp][0] = r0;  bf[2 * jp][1] = r1;
            bf[2 * jp + 1][0] = r2;  bf[2 * jp + 1][1] = r3;
        }
        #pragma unroll
        for (int i = 0; i < MI; i++)
            #pragma unroll
            for (int j = 0; j < NJ; j++)
                mma_bf16(acc[i][j], af[i][0], af[i][1], af[i][2], af[i][3],
                         bf[j][0], bf[j][1]);
    }

    // epilogue
    #pragma unroll
    for (int i = 0; i < MI; i++) {
        int r0 = m0 + wm + 16 * i + g;
        #pragma unroll
        for (int j = 0; j < NJ; j++) {
            int c = n0 + wn + 8 * j + 2 * lt;
            float bx = bias[c], by = bias[c + 1];
            float2 v0, v1;
            v0.x = acc[i][j][0] + bx;  v0.y = acc[i][j][1] + by;
            v1.x = acc[i][j][2] + bx;  v1.y = acc[i][j][3] + by;
            if (OP == 2) {
                float2 r0v = *(const float2*)(res + (size_t)r0 * N + c);
                float2 r1v = *(const float2*)(res + (size_t)(r0 + 8) * N + c);
                v0.x += r0v.x; v0.y += r0v.y;
                v1.x += r1v.x; v1.y += r1v.y;
            }
            if (OUTM & 1) {
                *(float2*)(C + (size_t)r0 * N + c) = v0;
                *(float2*)(C + (size_t)(r0 + 8) * N + c) = v1;
            }
            if (OUTM & 2) {
                *(unsigned*)(Cb + (size_t)r0 * N + c) = pk2(v0.x, v0.y);
                *(unsigned*)(Cb + (size_t)(r0 + 8) * N + c) = pk2(v1.x, v1.y);
            }
        }
    }
}

// ---------------------------------------------------------------------------
// In-place log_softmax over VOCAB=1024
// ---------------------------------------------------------------------------
__global__ void lsm_k(float* __restrict__ out)
{
    __shared__ float red[256];
    int n = blockIdx.x, t = threadIdx.x;
    float v[4];
    #pragma unroll
    for (int j = 0; j < 4; j++) v[j] = out[(size_t)n * NVOCAB + t + j * 256];

    float m = fmaxf(fmaxf(v[0], v[1]), fmaxf(v[2], v[3]));
    red[t] = m;
    __syncthreads();
    #pragma unroll
    for (int o = 128; o > 0; o >>= 1) {
        if (t < o) red[t] = fmaxf(red[t], red[t + o]);
        __syncthreads();
    }
    float M = red[0];
    __syncthreads();

    float s = 0.0f;
    #pragma unroll
    for (int j = 0; j < 4; j++) s += __expf(v[j] - M);
    red[t] = s;
    __syncthreads();
    #pragma unroll
    for (int o = 128; o > 0; o >>= 1) {
        if (t < o) red[t] += red[t + o];
        __syncthreads();
    }
    float lse = M + __logf(red[0]);

    #pragma unroll
    for (int j = 0; j < 4; j++)
        out[(size_t)n * NVOCAB + t + j * 256] = v[j] - lse;
}

// ---------------------------------------------------------------------------
// Launch
// ---------------------------------------------------------------------------
extern "C" void kernel_launch(void* const* d_in, const int* in_sizes, int n_in,
                              void* d_out, int out_size)
{
    const int*   tokens    = (const int*)  d_in[0];
    const int*   pos_idx   = (const int*)  d_in[1];
    const float* value_emb = (const float*)d_in[4];
    const float* coord_emb = (const float*)d_in[5];
    const float* pos_emb   = (const float*)d_in[6];
    const float* ln1_s     = (const float*)d_in[7];
    const float* ln1_b     = (const float*)d_in[8];
    const float* W_qkv     = (const float*)d_in[9];
    const float* b_qkv     = (const float*)d_in[10];
    const float* W_o       = (const float*)d_in[11];
    const float* b_o       = (const float*)d_in[12];
    const float* ln2_s     = (const float*)d_in[13];
    const float* ln2_b     = (const float*)d_in[14];
    const float* W_ff1     = (const float*)d_in[15];
    const float* b_ff1     = (const float*)d_in[16];
    const float* W_ff2     = (const float*)d_in[17];
    const float* b_ff2     = (const float*)d_in[18];
    const float* W_gen     = (const float*)d_in[19];
    const float* b_gen     = (const float*)d_in[20];
    float* out = (float*)d_out;

    float *x;
    bf16 *qkvb, *xn, *att, *mid, *xb;
    bf16 *wqkvb, *wob, *wf1b, *wf2b, *wgenb;
    cudaGetSymbolAddress((void**)&x,    g_x);
    cudaGetSymbolAddress((void**)&qkvb, g_qkvb);
    cudaGetSymbolAddress((void**)&xn,   g_xn);
    cudaGetSymbolAddress((void**)&att,  g_att);
    cudaGetSymbolAddress((void**)&mid,  g_mid);
    cudaGetSymbolAddress((void**)&xb,   g_xb);
    cudaGetSymbolAddress((void**)&wqkvb, g_wqkv);
    cudaGetSymbolAddress((void**)&wob,   g_wo);
    cudaGetSymbolAddress((void**)&wf1b,  g_wf1);
    cudaGetSymbolAddress((void**)&wf2b,  g_wf2);
    cudaGetSymbolAddress((void**)&wgenb, g_wgen);

    cvt5_k<<<1792, 256>>>((const float4*)W_qkv, (const float4*)W_o,
                          (const float4*)W_ff1, (const float4*)W_ff2,
                          (const float4*)W_gen,
                          (uint2*)wqkvb, (uint2*)wob, (uint2*)wf1b,
                          (uint2*)wf2b, (uint2*)wgenb);

    embed_k<<<NTOK, DMODEL>>>(tokens, pos_idx, value_emb, coord_emb, pos_emb, x);

    for (int l = 0; l < NLAYER; l++) {
        const bf16* wqkv = wqkvb + (size_t)l * DMODEL * 3 * DMODEL;
        const float* bqkv = b_qkv + (size_t)l * 3 * DMODEL;
        const bf16* wo    = wob   + (size_t)l * DMODEL * DMODEL;
        const float* bo   = b_o   + (size_t)l * DMODEL;
        const bf16* wf1   = wf1b  + (size_t)l * DMODEL * 4 * DMODEL;
        const float* bf1  = b_ff1 + (size_t)l * 4 * DMODEL;
        const bf16* wf2   = wf2b  + (size_t)l * 4 * DMODEL * DMODEL;
        const float* bf2  = b_ff2 + (size_t)l * DMODEL;

        ln_k<<<NTOK / 8, 256>>>(x, ln1_s + l * DMODEL, ln1_b + l * DMODEL, xn);

        { dim3 g(3 * DMODEL / 128, NTOK / 128);
          hg128_k<0, 2><<<g, 128>>>(xn, wqkv, bqkv, nullptr, nullptr, qkvb,
                                    NTOK, 3 * DMODEL, DMODEL); }

        attn_k<<<NBATCH * NHEAD, 128>>>(qkvb, att);

        { dim3 g(DMODEL / 128, NTOK / 64);
          hg64_k<2, 1><<<g, 256>>>(att, wo, bo, x, x, nullptr,
                                   NTOK, DMODEL, DMODEL); }

        ln_k<<<NTOK / 8, 256>>>(x, ln2_s + l * DMODEL, ln2_b + l * DMODEL, xn);

        { dim3 g(4 * DMODEL / 128, NTOK / 128);
          hg128_k<1, 2><<<g, 128>>>(xn, wf1, bf1, nullptr, nullptr, mid,
                                    NTOK, 4 * DMODEL, DMODEL); }

        { dim3 g(DMODEL / 128, NTOK / 64);
          hg64_k<2, 3><<<g, 256>>>(mid, wf2, bf2, x, x, xb,
                                   NTOK, DMODEL, 4 * DMODEL); }
    }

    { dim3 g(NVOCAB / 128, NTOK / 128);
      hg128_k<0, 1><<<g, 128>>>(xb, wgenb, b_gen, nullptr, out, nullptr,
                                NTOK, NVOCAB, DMODEL); }

    lsm_k<<<NTOK, 256>>>(out);
}